// round 14
// baseline (speedup 1.0000x reference)
#include <cuda_runtime.h>
#include <math.h>

#define BB 4
#define NN 4096
#define MM 4096
#define CCH 64
#define KK 32
#define RADIUS 0.1f
#define RAD2 0.01f
#define EPSV 1e-5f

// ---------------- device scratch ----------------
__device__ int      g_idx[BB * NN * KK];
__device__ unsigned g_nbr[BB * NN];
__device__ int      g_idxnn[BB * NN];
__device__ float    g_Wgeff[CCH * CCH];   // row-major [o][i]  (k_main)
__device__ float    g_WqiT[CCH * CCH];    // transposed [i][o] (k_pre)
__device__ float    g_WqjT[CCH * CCH];
__device__ float    g_WalT[CCH * CCH];
__device__ float    g_bconst[CCH];
__device__ float    g_Qi[BB * MM * CCH];
__device__ float    g_Qj[BB * MM * CCH];
__device__ float    g_AF[BB * MM * CCH];  // includes +b_al fold

// ---------------- warp-bitonic helpers ----------------
__device__ __forceinline__ void bsort32(float& d, int& ix, int lane) {
#pragma unroll
    for (int k = 2; k <= 32; k <<= 1) {
#pragma unroll
        for (int j = k >> 1; j > 0; j >>= 1) {
            float od = __shfl_xor_sync(0xffffffffu, d, j);
            int   oi = __shfl_xor_sync(0xffffffffu, ix, j);
            bool keepMin = (((lane & k) == 0) == ((lane & j) == 0));
            bool take = keepMin ? (od < d) : (od > d);
            if (take) { d = od; ix = oi; }
        }
    }
}
__device__ __forceinline__ void bmerge32(float& d, int& ix, int lane) {
#pragma unroll
    for (int j = 16; j > 0; j >>= 1) {
        float od = __shfl_xor_sync(0xffffffffu, d, j);
        int   oi = __shfl_xor_sync(0xffffffffu, ix, j);
        bool keepMin = ((lane & j) == 0);
        bool take = keepMin ? (od < d) : (od > d);
        if (take) { d = od; ix = oi; }
    }
}

__device__ __forceinline__ void knn_flush(float* bD, int* bI, float& bd, int& bi,
                                          float& thr, int& cnt, int lane) {
    __syncwarp();
    float nd = bD[lane]; int ni = bI[lane];
    bsort32(nd, ni, lane);
    float rd = __shfl_sync(0xffffffffu, nd, 31 ^ lane);
    int   ri = __shfl_sync(0xffffffffu, ni, 31 ^ lane);
    if (rd < bd) { bd = rd; bi = ri; }
    bmerge32(bd, bi, lane);
    thr = __shfl_sync(0xffffffffu, bd, 31);
    cnt -= 32;
    float sd = 0.f; int si = 0;
    if (lane < cnt) { sd = bD[32 + lane]; si = bI[32 + lane]; }
    __syncwarp();
    if (lane < cnt) { bD[lane] = sd; bI[lane] = si; }
    __syncwarp();
}

// ---------------- kernel 1: top-K, 2 queries per warp (R13, proven) ----------
constexpr int KNN_SM_FLOATS = 3 * MM + 16 * 64 * 2;   // 14336 floats

__global__ __launch_bounds__(256) void k_knn(const float* __restrict__ qxyz,
                                             const float* __restrict__ sxyz,
                                             const int* __restrict__ smask) {
    extern __shared__ float dsm[];
    float* sx = dsm;
    float* sy = dsm + MM;
    float* sz = dsm + 2 * MM;
    int b   = blockIdx.x >> 8;
    int grp = blockIdx.x & 255;
    for (int i = threadIdx.x; i < MM; i += 256) {
        bool v = smask[b * MM + i] > 0;
        float x = sxyz[(b * MM + i) * 3 + 0];
        float y = sxyz[(b * MM + i) * 3 + 1];
        float z = sxyz[(b * MM + i) * 3 + 2];
        sx[i] = v ? x : 1e18f;
        sy[i] = v ? y : 1e18f;
        sz[i] = v ? z : 1e18f;
    }
    __syncthreads();

    int warp = threadIdx.x >> 5, lane = threadIdx.x & 31;
    float* bD0 = dsm + 3 * MM + (warp * 2 + 0) * 64;
    float* bD1 = dsm + 3 * MM + (warp * 2 + 1) * 64;
    int*   bI0 = (int*)(dsm + 3 * MM + 1024) + (warp * 2 + 0) * 64;
    int*   bI1 = (int*)(dsm + 3 * MM + 1024) + (warp * 2 + 1) * 64;

    int n0  = grp * 16 + warp * 2;
    int qi0 = b * NN + n0;
    int qi1 = qi0 + 1;
    float qx0 = qxyz[qi0 * 3 + 0], qy0 = qxyz[qi0 * 3 + 1], qz0 = qxyz[qi0 * 3 + 2];
    float qx1 = qxyz[qi1 * 3 + 0], qy1 = qxyz[qi1 * 3 + 1], qz1 = qxyz[qi1 * 3 + 2];

    float bd0 = INFINITY, bd1 = INFINITY;
    int   bi0 = 0, bi1 = 0;
    float thr0 = INFINITY, thr1 = INFINITY;
    int   cnt0 = 0, cnt1 = 0;

    for (int ch = 0; ch < MM / 32; ++ch) {
        int m = ch * 32 + lane;
        float px = sx[m], py = sy[m], pz = sz[m];
        float dx0 = qx0 - px, dy0 = qy0 - py, dz0 = qz0 - pz;
        float dx1 = qx1 - px, dy1 = qy1 - py, dz1 = qz1 - pz;
        float d20 = fmaf(dx0, dx0, fmaf(dy0, dy0, dz0 * dz0));
        float d21 = fmaf(dx1, dx1, fmaf(dy1, dy1, dz1 * dz1));

        bool pass0 = d20 < thr0;
        unsigned mask0 = __ballot_sync(0xffffffffu, pass0);
        if (mask0) {
            int pos = cnt0 + __popc(mask0 & ((1u << lane) - 1u));
            if (pass0) { bD0[pos] = d20; bI0[pos] = m; }
            cnt0 += __popc(mask0);
            if (cnt0 >= 32) knn_flush(bD0, bI0, bd0, bi0, thr0, cnt0, lane);
        }
        bool pass1 = d21 < thr1;
        unsigned mask1 = __ballot_sync(0xffffffffu, pass1);
        if (mask1) {
            int pos = cnt1 + __popc(mask1 & ((1u << lane) - 1u));
            if (pass1) { bD1[pos] = d21; bI1[pos] = m; }
            cnt1 += __popc(mask1);
            if (cnt1 >= 32) knn_flush(bD1, bI1, bd1, bi1, thr1, cnt1, lane);
        }
    }
    if (cnt0 > 0) {
        __syncwarp();
        float nd = (lane < cnt0) ? bD0[lane] : INFINITY;
        int   ni = (lane < cnt0) ? bI0[lane] : 0;
        bsort32(nd, ni, lane);
        float rd = __shfl_sync(0xffffffffu, nd, 31 ^ lane);
        int   ri = __shfl_sync(0xffffffffu, ni, 31 ^ lane);
        if (rd < bd0) { bd0 = rd; bi0 = ri; }
        bmerge32(bd0, bi0, lane);
    }
    if (cnt1 > 0) {
        __syncwarp();
        float nd = (lane < cnt1) ? bD1[lane] : INFINITY;
        int   ni = (lane < cnt1) ? bI1[lane] : 0;
        bsort32(nd, ni, lane);
        float rd = __shfl_sync(0xffffffffu, nd, 31 ^ lane);
        int   ri = __shfl_sync(0xffffffffu, ni, 31 ^ lane);
        if (rd < bd1) { bd1 = rd; bi1 = ri; }
        bmerge32(bd1, bi1, lane);
    }
    g_idx[qi0 * KK + lane] = bi0;
    g_idx[qi1 * KK + lane] = bi1;
    unsigned nb0 = __ballot_sync(0xffffffffu, bd0 <= RAD2);
    unsigned nb1 = __ballot_sync(0xffffffffu, bd1 <= RAD2);
    if (lane == 0) {
        g_nbr[qi0] = nb0; g_idxnn[qi0] = bi0;
        g_nbr[qi1] = nb1; g_idxnn[qi1] = bi1;
    }
}

// ---------------- kernel 2a/2b: compose ----------------
__global__ void k_compose1(const float* __restrict__ Wg1,
                           const float* __restrict__ Wg2,
                           const float* __restrict__ Wal) {
    int e = blockIdx.x * 256 + threadIdx.x;
    int o = e >> 6, i = e & 63;
    float a = 0.f;
    for (int c = 0; c < 64; ++c)
        a = fmaf(Wg2[o * 64 + c], Wg1[c * 64 + i], a);
    g_Wgeff[e] = a;
    g_WalT[i * 64 + o] = Wal[e];
}

__global__ void k_compose2(const float* __restrict__ Wphi,
                           const float* __restrict__ Wpsi,
                           const float* __restrict__ bphi,
                           const float* __restrict__ bpsi,
                           const float* __restrict__ bg1,
                           const float* __restrict__ bg2,
                           const float* __restrict__ Wg2) {
    int e = blockIdx.x * 256 + threadIdx.x;
    int o = e >> 6, i = e & 63;
    float qi = 0.f, qj = 0.f;
    for (int c = 0; c < 64; ++c) {
        float g = g_Wgeff[o * 64 + c];
        qi = fmaf(g, Wphi[c * 64 + i], qi);
        qj = fmaf(g, Wpsi[c * 64 + i], qj);
    }
    g_WqiT[i * 64 + o] = qi;
    g_WqjT[i * 64 + o] = qj;
    if (e < 64) {
        float a = bg2[e];
        for (int c = 0; c < 64; ++c)
            a = fmaf(Wg2[e * 64 + c], bg1[c], a);
        for (int j = 0; j < 64; ++j)
            a = fmaf(g_Wgeff[e * 64 + j], bphi[j] - bpsi[j], a);
        g_bconst[e] = a;
    }
}

// ---------------- kernel 3: per-support precompute (256 thr, 128 pts/block) ---
#define STRD 36
#define KSTR 132
constexpr int PRE_WQI = 0, PRE_WQJ = 4096, PRE_WAL = 8192, PRE_X = 12288;
constexpr int PRE_SM = PRE_X + 64 * KSTR;   // 20736 floats = 82944 B

__global__ __launch_bounds__(256) void k_pre(const float* __restrict__ feat,
                                             const float* __restrict__ bal) {
    extern __shared__ float s[];
    int tid = threadIdx.x;

    for (int i = tid; i < 4096; i += 256) {
        s[PRE_WQI + i] = g_WqiT[i];
        s[PRE_WQJ + i] = g_WqjT[i];
        s[PRE_WAL + i] = g_WalT[i];
    }

    int base = blockIdx.x * 128;              // 128 blocks, 128 points each
    int b    = base >> 12;
    int m0   = base & (MM - 1);
    float* xS = s + PRE_X;
    for (int i = tid; i < 8192; i += 256) {
        int k = i & 127, cc = i >> 7;
        xS[cc * KSTR + k] = feat[((long)b * CCH + cc) * MM + m0 + k];
    }
    __syncthreads();

    int cq = tid >> 4;            // 0..15
    int g  = tid & 15;            // 0..15 (16 k-groups of 8 over 128 points)
    int c0 = cq * 4;
    int k0 = g * 8;

    float4 aqi[8], aqj[8], aaf[8];
#pragma unroll
    for (int kk = 0; kk < 8; ++kk) {
        aqi[kk] = make_float4(0.f, 0.f, 0.f, 0.f);
        aqj[kk] = make_float4(0.f, 0.f, 0.f, 0.f);
        aaf[kk] = make_float4(0.f, 0.f, 0.f, 0.f);
    }
    {
        const float* Wi = s + PRE_WQI + c0;
        const float* Wj = s + PRE_WQJ + c0;
        const float* Wa = s + PRE_WAL + c0;
        const float* xb = xS + k0;
#pragma unroll 4
        for (int c2 = 0; c2 < 64; ++c2) {
            float4 wi4 = *(const float4*)(Wi + c2 * 64);
            float4 wj4 = *(const float4*)(Wj + c2 * 64);
            float4 wa4 = *(const float4*)(Wa + c2 * 64);
            float4 x0 = *(const float4*)(xb + c2 * KSTR);
            float4 x1 = *(const float4*)(xb + c2 * KSTR + 4);
#pragma unroll
            for (int kk = 0; kk < 8; ++kk) {
                float xv = (kk < 4) ? (&x0.x)[kk] : (&x1.x)[kk - 4];
                aqi[kk].x = fmaf(wi4.x, xv, aqi[kk].x);
                aqi[kk].y = fmaf(wi4.y, xv, aqi[kk].y);
                aqi[kk].z = fmaf(wi4.z, xv, aqi[kk].z);
                aqi[kk].w = fmaf(wi4.w, xv, aqi[kk].w);
                aqj[kk].x = fmaf(wj4.x, xv, aqj[kk].x);
                aqj[kk].y = fmaf(wj4.y, xv, aqj[kk].y);
                aqj[kk].z = fmaf(wj4.z, xv, aqj[kk].z);
                aqj[kk].w = fmaf(wj4.w, xv, aqj[kk].w);
                aaf[kk].x = fmaf(wa4.x, xv, aaf[kk].x);
                aaf[kk].y = fmaf(wa4.y, xv, aaf[kk].y);
                aaf[kk].z = fmaf(wa4.z, xv, aaf[kk].z);
                aaf[kk].w = fmaf(wa4.w, xv, aaf[kk].w);
            }
        }
    }
    float4 balv = *(const float4*)(bal + c0);
#pragma unroll
    for (int kk = 0; kk < 8; ++kk) {
        long o = (long)(base + k0 + kk) * 64 + c0;
        *(float4*)(g_Qi + o) = aqi[kk];
        *(float4*)(g_Qj + o) = aqj[kk];
        float4 af = aaf[kk];
        af.x += balv.x; af.y += balv.y; af.z += balv.z; af.w += balv.w;
        *(float4*)(g_AF + o) = af;
    }
}

// ---------------- kernel 4: fused per-query, double-buffered ----------------
struct P2 {
    const float *qxyz, *sxyz;
    const int   *qmask;
    const float *Wth1, *bth1, *Wth2, *bth2;
    const float *gt, *bet, *rmt, *rvt, *gg, *beg, *rmg, *rvg;
    float* out;
};

constexpr int OFF_WG   = 0;
constexpr int OFF_WEFF = 4096;
constexpr int OFF_CC   = 4352;
constexpr int OFF_BN   = 4416;
constexpr int OFF_Q    = 4672;
constexpr int QO_DL = 0, QO_POS = 2304, QO_FM = 2432, QO_KIDX = 2464;
constexpr int QSZ = 2496;
constexpr int SMEM_FLOATS = OFF_Q + 8 * QSZ;   // 24640 floats = 98560 B

__global__ __launch_bounds__(128, 2) void k_main(P2 p) {
    extern __shared__ float sm[];
    int tid = threadIdx.x;

    {
        for (int i = tid; i < 4096; i += 128) {
            int o = i >> 6, in = i & 63;
            sm[OFF_WG + in * 64 + o] = g_Wgeff[i];
        }
        for (int i = tid; i < 256; i += 128) {
            int cc = i >> 2, j = i & 3;
            float acc;
            if (j < 3) {
                acc = 0.f;
                for (int c2 = 0; c2 < 64; ++c2)
                    acc = fmaf(p.Wth2[cc * 64 + c2], p.Wth1[c2 * 3 + j], acc);
            } else {
                acc = p.bth2[cc];
                for (int c2 = 0; c2 < 64; ++c2)
                    acc = fmaf(p.Wth2[cc * 64 + c2], p.bth1[c2], acc);
            }
            sm[OFF_WEFF + cc * 4 + j] = acc;
        }
        if (tid < 64) {
            int i = tid;
            sm[OFF_CC + i] = g_bconst[i];
            float it = p.gt[i] * rsqrtf(p.rvt[i] + EPSV);
            sm[OFF_BN + 0 * 64 + i] = it;
            sm[OFF_BN + 1 * 64 + i] = p.bet[i] - p.rmt[i] * it;
            float ig = p.gg[i] * rsqrtf(p.rvg[i] + EPSV);
            sm[OFF_BN + 2 * 64 + i] = ig;
            sm[OFF_BN + 3 * 64 + i] = p.beg[i] - p.rmg[i] * ig;
        }
    }
    __syncthreads();

    int pr = tid >> 6;
    int t  = tid & 63;
    int g  = t & 7;
    int cq = t >> 3;
    int c0 = cq * 8;
    int k0 = g * 4;

    const int ngrp = (BB * NN) / 4;

    // setup lambda: all 128 threads; qq = tid>>5, k = tid&31
    auto do_setup = [&](int grp, int cbuf) {
        int qq = tid >> 5;
        int k  = tid & 31;
        int qi = grp * 4 + qq;
        int bb = qi >> 12;
        long rb = (long)bb * MM;
        float* Q = sm + OFF_Q + (cbuf * 4 + qq) * QSZ;
        int ki = g_idx[qi * KK + k];
        ((int*)(Q + QO_KIDX))[k] = ki;
        float qx = p.qxyz[qi * 3 + 0];
        float qy = p.qxyz[qi * 3 + 1];
        float qz = p.qxyz[qi * 3 + 2];
        const float* s = p.sxyz + (rb + ki) * 3;
        float4 pp;
        pp.x = (s[0] - qx) * (1.0f / RADIUS);
        pp.y = (s[1] - qy) * (1.0f / RADIUS);
        pp.z = (s[2] - qz) * (1.0f / RADIUS);
        pp.w = 0.f;
        *(float4*)(Q + QO_POS + k * 4) = pp;
        unsigned nb = g_nbr[qi];
        int qm = p.qmask[qi];
        (Q + QO_FM)[k] = (float)((nb >> k) & 1u) + (1.0f - (float)qm);
    };

    int c = 0;
    if (blockIdx.x < ngrp) do_setup(blockIdx.x, 0);

    for (int grp = blockIdx.x; grp < ngrp; grp += gridDim.x) {
        __syncthreads();   // S_a: cur setup visible; prior epilogue done with next buf
        int b  = (grp * 4) >> 12;
        long rowbase = (long)b * MM;
        float* QA = sm + OFF_Q + (c * 4 + pr * 2 + 0) * QSZ;
        float* QB = sm + OFF_Q + (c * 4 + pr * 2 + 1) * QSZ;

        // ---- delta ----
        {
            float4 invtL = *(const float4*)(sm + OFF_BN + 0 * 64 + c0);
            float4 invtH = *(const float4*)(sm + OFF_BN + 0 * 64 + c0 + 4);
            float4 shtL  = *(const float4*)(sm + OFF_BN + 1 * 64 + c0);
            float4 shtH  = *(const float4*)(sm + OFF_BN + 1 * 64 + c0 + 4);
            float4 pA[4], pB[4];
#pragma unroll
            for (int kk = 0; kk < 4; ++kk) {
                pA[kk] = *(const float4*)(QA + QO_POS + (k0 + kk) * 4);
                pB[kk] = *(const float4*)(QB + QO_POS + (k0 + kk) * 4);
            }
#pragma unroll
            for (int j = 0; j < 8; ++j) {
                float4 wej = *(const float4*)(sm + OFF_WEFF + (c0 + j) * 4);
                float it = (j < 4) ? (&invtL.x)[j] : (&invtH.x)[j - 4];
                float sh = (j < 4) ? (&shtL.x)[j] : (&shtH.x)[j - 4];
                float4 rA, rB;
#pragma unroll
                for (int kk = 0; kk < 4; ++kk) {
                    float dA = wej.w, dB = wej.w;
                    dA = fmaf(wej.x, pA[kk].x, dA); dB = fmaf(wej.x, pB[kk].x, dB);
                    dA = fmaf(wej.y, pA[kk].y, dA); dB = fmaf(wej.y, pB[kk].y, dB);
                    dA = fmaf(wej.z, pA[kk].z, dA); dB = fmaf(wej.z, pB[kk].z, dB);
                    (&rA.x)[kk] = fmaxf(fmaf(dA, it, sh), 0.f);
                    (&rB.x)[kk] = fmaxf(fmaf(dB, it, sh), 0.f);
                }
                *(float4*)(QA + QO_DL + (c0 + j) * STRD + k0) = rA;
                *(float4*)(QB + QO_DL + (c0 + j) * STRD + k0) = rB;
            }
        }
        __syncthreads();   // S_b: dl visible

        // ---- matvec ----
        float accA[32], accB[32];
#pragma unroll
        for (int i = 0; i < 32; ++i) { accA[i] = 0.f; accB[i] = 0.f; }
        {
            const float* W  = sm + OFF_WG + c0;
            const float* dA = QA + QO_DL + k0;
            const float* dB = QB + QO_DL + k0;
#pragma unroll 2
            for (int c2 = 0; c2 < 64; ++c2) {
                float4 w0 = *(const float4*)(W + c2 * 64);
                float4 w1 = *(const float4*)(W + c2 * 64 + 4);
                float4 a4 = *(const float4*)(dA + c2 * STRD);
                float4 b4 = *(const float4*)(dB + c2 * STRD);
#pragma unroll
                for (int j = 0; j < 8; ++j) {
                    float w = (j < 4) ? (&w0.x)[j] : (&w1.x)[j - 4];
                    accA[j * 4 + 0] = fmaf(w, a4.x, accA[j * 4 + 0]);
                    accA[j * 4 + 1] = fmaf(w, a4.y, accA[j * 4 + 1]);
                    accA[j * 4 + 2] = fmaf(w, a4.z, accA[j * 4 + 2]);
                    accA[j * 4 + 3] = fmaf(w, a4.w, accA[j * 4 + 3]);
                    accB[j * 4 + 0] = fmaf(w, b4.x, accB[j * 4 + 0]);
                    accB[j * 4 + 1] = fmaf(w, b4.y, accB[j * 4 + 1]);
                    accB[j * 4 + 2] = fmaf(w, b4.z, accB[j * 4 + 2]);
                    accB[j * 4 + 3] = fmaf(w, b4.w, accB[j * 4 + 3]);
                }
            }
        }

        // ---- overlapped setup for next group (writes OTHER buffer) ----
        int gn = grp + gridDim.x;
        if (gn < ngrp) do_setup(gn, c ^ 1);

        // ---- epilogue ----
        float4 bcnL  = *(const float4*)(sm + OFF_CC + c0);
        float4 bcnH  = *(const float4*)(sm + OFF_CC + c0 + 4);
        float4 invgL = *(const float4*)(sm + OFF_BN + 2 * 64 + c0);
        float4 invgH = *(const float4*)(sm + OFF_BN + 2 * 64 + c0 + 4);
        float4 shgL  = *(const float4*)(sm + OFF_BN + 3 * 64 + c0);
        float4 shgH  = *(const float4*)(sm + OFF_BN + 3 * 64 + c0 + 4);
#pragma unroll
        for (int qq = 0; qq < 2; ++qq) {
            int qi = grp * 4 + pr * 2 + qq;
            int n  = qi & (NN - 1);
            float* Q = qq ? QB : QA;
            float* acc = qq ? accB : accA;
            int* kidx = (int*)(Q + QO_KIDX);
            float* fmB = Q + QO_FM;

            float4 dl4[8];
#pragma unroll
            for (int j = 0; j < 8; ++j)
                dl4[j] = *(const float4*)(Q + QO_DL + (c0 + j) * STRD + k0);

            int nn = g_idxnn[qi];
            float4 qiL = *(const float4*)(g_Qi + (rowbase + nn) * 64 + c0);
            float4 qiH = *(const float4*)(g_Qi + (rowbase + nn) * 64 + c0 + 4);
            float se[8] = {0.f, 0.f, 0.f, 0.f, 0.f, 0.f, 0.f, 0.f};
            float sf[8] = {0.f, 0.f, 0.f, 0.f, 0.f, 0.f, 0.f, 0.f};
#pragma unroll
            for (int kk = 0; kk < 4; ++kk) {
                int k = k0 + kk;
                int ridx = kidx[k];
                float4 qjL = *(const float4*)(g_Qj + (rowbase + ridx) * 64 + c0);
                float4 qjH = *(const float4*)(g_Qj + (rowbase + ridx) * 64 + c0 + 4);
                float4 afL = *(const float4*)(g_AF + (rowbase + ridx) * 64 + c0);
                float4 afH = *(const float4*)(g_AF + (rowbase + ridx) * 64 + c0 + 4);
                float fm = fmB[k];
#pragma unroll
                for (int j = 0; j < 8; ++j) {
                    float qiv = (j < 4) ? (&qiL.x)[j] : (&qiH.x)[j - 4];
                    float qjv = (j < 4) ? (&qjL.x)[j] : (&qjH.x)[j - 4];
                    float afv = (j < 4) ? (&afL.x)[j] : (&afH.x)[j - 4];
                    float bc  = (j < 4) ? (&bcnL.x)[j] : (&bcnH.x)[j - 4];
                    float ig  = (j < 4) ? (&invgL.x)[j] : (&invgH.x)[j - 4];
                    float sg  = (j < 4) ? (&shgL.x)[j] : (&shgH.x)[j - 4];
                    float pre2 = qiv - qjv + acc[j * 4 + kk] + bc;
                    float v = fmaxf(fmaf(pre2, ig, sg), 0.f);
                    float e = __expf(v);
                    float ftv = (afv + (&dl4[j].x)[kk]) * fm;
                    se[j] += e;
                    sf[j] = fmaf(e, ftv, sf[j]);
                }
            }
#pragma unroll
            for (int j = 0; j < 8; ++j) {
                float s1 = se[j], s2 = sf[j];
                s1 += __shfl_xor_sync(0xffffffffu, s1, 1);
                s2 += __shfl_xor_sync(0xffffffffu, s2, 1);
                s1 += __shfl_xor_sync(0xffffffffu, s1, 2);
                s2 += __shfl_xor_sync(0xffffffffu, s2, 2);
                s1 += __shfl_xor_sync(0xffffffffu, s1, 4);
                s2 += __shfl_xor_sync(0xffffffffu, s2, 4);
                if (g == 0)
                    p.out[((long)b * CCH + c0 + j) * NN + n] = s2 / s1;
            }
        }
        c ^= 1;
    }
}

// ---------------- host launcher ----------------
extern "C" void kernel_launch(void* const* d_in, const int* in_sizes, int n_in,
                              void* d_out, int out_size) {
    const float* qxyz  = (const float*)d_in[0];
    const float* sxyz  = (const float*)d_in[1];
    const int*   qmask = (const int*)d_in[2];
    const int*   smask = (const int*)d_in[3];
    const float* feat  = (const float*)d_in[4];
    const float* Wth1  = (const float*)d_in[5];
    const float* bth1  = (const float*)d_in[6];
    const float* Wth2  = (const float*)d_in[7];
    const float* bth2  = (const float*)d_in[8];
    const float* Wphi  = (const float*)d_in[9];
    const float* bphi  = (const float*)d_in[10];
    const float* Wpsi  = (const float*)d_in[11];
    const float* bpsi  = (const float*)d_in[12];
    const float* Wal   = (const float*)d_in[13];
    const float* bal   = (const float*)d_in[14];
    const float* Wg1   = (const float*)d_in[15];
    const float* bg1   = (const float*)d_in[16];
    const float* Wg2   = (const float*)d_in[17];
    const float* bg2   = (const float*)d_in[18];

    P2 p;
    p.qxyz = qxyz; p.sxyz = sxyz; p.qmask = qmask;
    p.Wth1 = Wth1; p.bth1 = bth1; p.Wth2 = Wth2; p.bth2 = bth2;
    p.gt   = (const float*)d_in[19]; p.bet  = (const float*)d_in[20];
    p.rmt  = (const float*)d_in[21]; p.rvt  = (const float*)d_in[22];
    p.gg   = (const float*)d_in[23]; p.beg  = (const float*)d_in[24];
    p.rmg  = (const float*)d_in[25]; p.rvg  = (const float*)d_in[26];
    p.out  = (float*)d_out;

    k_compose1<<<16, 256>>>(Wg1, Wg2, Wal);
    k_compose2<<<16, 256>>>(Wphi, Wpsi, bphi, bpsi, bg1, bg2, Wg2);

    cudaFuncSetAttribute(k_knn, cudaFuncAttributeMaxDynamicSharedMemorySize,
                         KNN_SM_FLOATS * 4);
    k_knn<<<(BB * NN) / 16, 256, KNN_SM_FLOATS * 4>>>(qxyz, sxyz, smask);

    cudaFuncSetAttribute(k_pre, cudaFuncAttributeMaxDynamicSharedMemorySize,
                         PRE_SM * 4);
    k_pre<<<(BB * MM) / 128, 256, PRE_SM * 4>>>(feat, bal);

    cudaFuncSetAttribute(k_main, cudaFuncAttributeMaxDynamicSharedMemorySize,
                         SMEM_FLOATS * 4);
    int dev = 0, nsm = 148;
    cudaGetDevice(&dev);
    cudaDeviceGetAttribute(&nsm, cudaDevAttrMultiProcessorCount, dev);
    k_main<<<2 * nsm, 128, SMEM_FLOATS * 4>>>(p);
}

// round 15
// speedup vs baseline: 1.0104x; 1.0104x over previous
#include <cuda_runtime.h>
#include <math.h>

#define BB 4
#define NN 4096
#define MM 4096
#define CCH 64
#define KK 32
#define RADIUS 0.1f
#define RAD2 0.01f
#define EPSV 1e-5f

typedef unsigned long long u64;
__device__ __forceinline__ u64 pk2(float w) {
    u64 r; asm("mov.b64 %0, {%1, %1};" : "=l"(r) : "f"(w)); return r;
}
#define FMA2(d, a, b) asm("fma.rn.f32x2 %0, %1, %2, %0;" : "+l"(d) : "l"(a), "l"(b))
#define UNPK(lo, hi, v) asm("mov.b64 {%0, %1}, %2;" : "=f"(lo), "=f"(hi) : "l"(v))

// ---------------- device scratch ----------------
__device__ int      g_idx[BB * NN * KK];
__device__ unsigned g_nbr[BB * NN];
__device__ int      g_idxnn[BB * NN];
__device__ float    g_Wgeff[CCH * CCH];
__device__ float    g_WqiT[CCH * CCH];
__device__ float    g_WqjT[CCH * CCH];
__device__ float    g_WalT[CCH * CCH];
__device__ float    g_bconst[CCH];
__device__ float    g_Qi[BB * MM * CCH];
__device__ float    g_Qj[BB * MM * CCH];
__device__ float    g_AF[BB * MM * CCH];

// ---------------- warp-bitonic helpers ----------------
__device__ __forceinline__ void bsort32(float& d, int& ix, int lane) {
#pragma unroll
    for (int k = 2; k <= 32; k <<= 1) {
#pragma unroll
        for (int j = k >> 1; j > 0; j >>= 1) {
            float od = __shfl_xor_sync(0xffffffffu, d, j);
            int   oi = __shfl_xor_sync(0xffffffffu, ix, j);
            bool keepMin = (((lane & k) == 0) == ((lane & j) == 0));
            bool take = keepMin ? (od < d) : (od > d);
            if (take) { d = od; ix = oi; }
        }
    }
}
__device__ __forceinline__ void bmerge32(float& d, int& ix, int lane) {
#pragma unroll
    for (int j = 16; j > 0; j >>= 1) {
        float od = __shfl_xor_sync(0xffffffffu, d, j);
        int   oi = __shfl_xor_sync(0xffffffffu, ix, j);
        bool keepMin = ((lane & j) == 0);
        bool take = keepMin ? (od < d) : (od > d);
        if (take) { d = od; ix = oi; }
    }
}

__device__ __forceinline__ void knn_flush(float* bD, int* bI, float& bd, int& bi,
                                          float& thr, int& cnt, int lane) {
    __syncwarp();
    float nd = bD[lane]; int ni = bI[lane];
    bsort32(nd, ni, lane);
    float rd = __shfl_sync(0xffffffffu, nd, 31 ^ lane);
    int   ri = __shfl_sync(0xffffffffu, ni, 31 ^ lane);
    if (rd < bd) { bd = rd; bi = ri; }
    bmerge32(bd, bi, lane);
    thr = __shfl_sync(0xffffffffu, bd, 31);
    cnt -= 32;
    float sd = 0.f; int si = 0;
    if (lane < cnt) { sd = bD[32 + lane]; si = bI[32 + lane]; }
    __syncwarp();
    if (lane < cnt) { bD[lane] = sd; bI[lane] = si; }
    __syncwarp();
}

// ---------------- kernel 1: top-K, 2 queries per warp (R13, proven) ----------
constexpr int KNN_SM_FLOATS = 3 * MM + 16 * 64 * 2;

__global__ __launch_bounds__(256) void k_knn(const float* __restrict__ qxyz,
                                             const float* __restrict__ sxyz,
                                             const int* __restrict__ smask) {
    extern __shared__ float dsm[];
    float* sx = dsm;
    float* sy = dsm + MM;
    float* sz = dsm + 2 * MM;
    int b   = blockIdx.x >> 8;
    int grp = blockIdx.x & 255;
    for (int i = threadIdx.x; i < MM; i += 256) {
        bool v = smask[b * MM + i] > 0;
        float x = sxyz[(b * MM + i) * 3 + 0];
        float y = sxyz[(b * MM + i) * 3 + 1];
        float z = sxyz[(b * MM + i) * 3 + 2];
        sx[i] = v ? x : 1e18f;
        sy[i] = v ? y : 1e18f;
        sz[i] = v ? z : 1e18f;
    }
    __syncthreads();

    int warp = threadIdx.x >> 5, lane = threadIdx.x & 31;
    float* bD0 = dsm + 3 * MM + (warp * 2 + 0) * 64;
    float* bD1 = dsm + 3 * MM + (warp * 2 + 1) * 64;
    int*   bI0 = (int*)(dsm + 3 * MM + 1024) + (warp * 2 + 0) * 64;
    int*   bI1 = (int*)(dsm + 3 * MM + 1024) + (warp * 2 + 1) * 64;

    int n0  = grp * 16 + warp * 2;
    int qi0 = b * NN + n0;
    int qi1 = qi0 + 1;
    float qx0 = qxyz[qi0 * 3 + 0], qy0 = qxyz[qi0 * 3 + 1], qz0 = qxyz[qi0 * 3 + 2];
    float qx1 = qxyz[qi1 * 3 + 0], qy1 = qxyz[qi1 * 3 + 1], qz1 = qxyz[qi1 * 3 + 2];

    float bd0 = INFINITY, bd1 = INFINITY;
    int   bi0 = 0, bi1 = 0;
    float thr0 = INFINITY, thr1 = INFINITY;
    int   cnt0 = 0, cnt1 = 0;

    for (int ch = 0; ch < MM / 32; ++ch) {
        int m = ch * 32 + lane;
        float px = sx[m], py = sy[m], pz = sz[m];
        float dx0 = qx0 - px, dy0 = qy0 - py, dz0 = qz0 - pz;
        float dx1 = qx1 - px, dy1 = qy1 - py, dz1 = qz1 - pz;
        float d20 = fmaf(dx0, dx0, fmaf(dy0, dy0, dz0 * dz0));
        float d21 = fmaf(dx1, dx1, fmaf(dy1, dy1, dz1 * dz1));

        bool pass0 = d20 < thr0;
        unsigned mask0 = __ballot_sync(0xffffffffu, pass0);
        if (mask0) {
            int pos = cnt0 + __popc(mask0 & ((1u << lane) - 1u));
            if (pass0) { bD0[pos] = d20; bI0[pos] = m; }
            cnt0 += __popc(mask0);
            if (cnt0 >= 32) knn_flush(bD0, bI0, bd0, bi0, thr0, cnt0, lane);
        }
        bool pass1 = d21 < thr1;
        unsigned mask1 = __ballot_sync(0xffffffffu, pass1);
        if (mask1) {
            int pos = cnt1 + __popc(mask1 & ((1u << lane) - 1u));
            if (pass1) { bD1[pos] = d21; bI1[pos] = m; }
            cnt1 += __popc(mask1);
            if (cnt1 >= 32) knn_flush(bD1, bI1, bd1, bi1, thr1, cnt1, lane);
        }
    }
    if (cnt0 > 0) {
        __syncwarp();
        float nd = (lane < cnt0) ? bD0[lane] : INFINITY;
        int   ni = (lane < cnt0) ? bI0[lane] : 0;
        bsort32(nd, ni, lane);
        float rd = __shfl_sync(0xffffffffu, nd, 31 ^ lane);
        int   ri = __shfl_sync(0xffffffffu, ni, 31 ^ lane);
        if (rd < bd0) { bd0 = rd; bi0 = ri; }
        bmerge32(bd0, bi0, lane);
    }
    if (cnt1 > 0) {
        __syncwarp();
        float nd = (lane < cnt1) ? bD1[lane] : INFINITY;
        int   ni = (lane < cnt1) ? bI1[lane] : 0;
        bsort32(nd, ni, lane);
        float rd = __shfl_sync(0xffffffffu, nd, 31 ^ lane);
        int   ri = __shfl_sync(0xffffffffu, ni, 31 ^ lane);
        if (rd < bd1) { bd1 = rd; bi1 = ri; }
        bmerge32(bd1, bi1, lane);
    }
    g_idx[qi0 * KK + lane] = bi0;
    g_idx[qi1 * KK + lane] = bi1;
    unsigned nb0 = __ballot_sync(0xffffffffu, bd0 <= RAD2);
    unsigned nb1 = __ballot_sync(0xffffffffu, bd1 <= RAD2);
    if (lane == 0) {
        g_nbr[qi0] = nb0; g_idxnn[qi0] = bi0;
        g_nbr[qi1] = nb1; g_idxnn[qi1] = bi1;
    }
}

// ---------------- kernel 2a/2b: compose ----------------
__global__ void k_compose1(const float* __restrict__ Wg1,
                           const float* __restrict__ Wg2,
                           const float* __restrict__ Wal) {
    int e = blockIdx.x * 256 + threadIdx.x;
    int o = e >> 6, i = e & 63;
    float a = 0.f;
    for (int c = 0; c < 64; ++c)
        a = fmaf(Wg2[o * 64 + c], Wg1[c * 64 + i], a);
    g_Wgeff[e] = a;
    g_WalT[i * 64 + o] = Wal[e];
}

__global__ void k_compose2(const float* __restrict__ Wphi,
                           const float* __restrict__ Wpsi,
                           const float* __restrict__ bphi,
                           const float* __restrict__ bpsi,
                           const float* __restrict__ bg1,
                           const float* __restrict__ bg2,
                           const float* __restrict__ Wg2) {
    int e = blockIdx.x * 256 + threadIdx.x;
    int o = e >> 6, i = e & 63;
    float qi = 0.f, qj = 0.f;
    for (int c = 0; c < 64; ++c) {
        float g = g_Wgeff[o * 64 + c];
        qi = fmaf(g, Wphi[c * 64 + i], qi);
        qj = fmaf(g, Wpsi[c * 64 + i], qj);
    }
    g_WqiT[i * 64 + o] = qi;
    g_WqjT[i * 64 + o] = qj;
    if (e < 64) {
        float a = bg2[e];
        for (int c = 0; c < 64; ++c)
            a = fmaf(Wg2[e * 64 + c], bg1[c], a);
        for (int j = 0; j < 64; ++j)
            a = fmaf(g_Wgeff[e * 64 + j], bphi[j] - bpsi[j], a);
        g_bconst[e] = a;
    }
}

// ---------------- kernel 3: per-support precompute (R13: 128 thr, 64 pts) ----
#define STRD 36
#define KSTR 68
constexpr int PRE_WQI = 0, PRE_WQJ = 4096, PRE_WAL = 8192, PRE_X = 12288;
constexpr int PRE_SM = PRE_X + 64 * KSTR;   // 16640 floats

__global__ __launch_bounds__(128) void k_pre(const float* __restrict__ feat,
                                             const float* __restrict__ bal) {
    extern __shared__ float s[];
    int tid = threadIdx.x;

    for (int i = tid; i < 4096; i += 128) {
        s[PRE_WQI + i] = g_WqiT[i];
        s[PRE_WQJ + i] = g_WqjT[i];
        s[PRE_WAL + i] = g_WalT[i];
    }

    int base = blockIdx.x * 64;
    int b    = base >> 12;
    int m0   = base & (MM - 1);
    float* xS = s + PRE_X;
    for (int i = tid; i < 4096; i += 128) {
        int k = i & 63, cc = i >> 6;
        xS[cc * KSTR + k] = feat[((long)b * CCH + cc) * MM + m0 + k];
    }
    __syncthreads();

    int cq = tid >> 3;
    int g  = tid & 7;
    int c0 = cq * 4;
    int k0 = g * 8;

    float4 aqi[8], aqj[8], aaf[8];
#pragma unroll
    for (int kk = 0; kk < 8; ++kk) {
        aqi[kk] = make_float4(0.f, 0.f, 0.f, 0.f);
        aqj[kk] = make_float4(0.f, 0.f, 0.f, 0.f);
        aaf[kk] = make_float4(0.f, 0.f, 0.f, 0.f);
    }
    {
        const float* Wi = s + PRE_WQI + c0;
        const float* Wj = s + PRE_WQJ + c0;
        const float* Wa = s + PRE_WAL + c0;
        const float* xb = xS + k0;
#pragma unroll 4
        for (int c2 = 0; c2 < 64; ++c2) {
            float4 wi4 = *(const float4*)(Wi + c2 * 64);
            float4 wj4 = *(const float4*)(Wj + c2 * 64);
            float4 wa4 = *(const float4*)(Wa + c2 * 64);
            float4 x0 = *(const float4*)(xb + c2 * KSTR);
            float4 x1 = *(const float4*)(xb + c2 * KSTR + 4);
#pragma unroll
            for (int kk = 0; kk < 8; ++kk) {
                float xv = (kk < 4) ? (&x0.x)[kk] : (&x1.x)[kk - 4];
                aqi[kk].x = fmaf(wi4.x, xv, aqi[kk].x);
                aqi[kk].y = fmaf(wi4.y, xv, aqi[kk].y);
                aqi[kk].z = fmaf(wi4.z, xv, aqi[kk].z);
                aqi[kk].w = fmaf(wi4.w, xv, aqi[kk].w);
                aqj[kk].x = fmaf(wj4.x, xv, aqj[kk].x);
                aqj[kk].y = fmaf(wj4.y, xv, aqj[kk].y);
                aqj[kk].z = fmaf(wj4.z, xv, aqj[kk].z);
                aqj[kk].w = fmaf(wj4.w, xv, aqj[kk].w);
                aaf[kk].x = fmaf(wa4.x, xv, aaf[kk].x);
                aaf[kk].y = fmaf(wa4.y, xv, aaf[kk].y);
                aaf[kk].z = fmaf(wa4.z, xv, aaf[kk].z);
                aaf[kk].w = fmaf(wa4.w, xv, aaf[kk].w);
            }
        }
    }
    float4 balv = *(const float4*)(bal + c0);
#pragma unroll
    for (int kk = 0; kk < 8; ++kk) {
        long o = (long)(base + k0 + kk) * 64 + c0;
        *(float4*)(g_Qi + o) = aqi[kk];
        *(float4*)(g_Qj + o) = aqj[kk];
        float4 af = aaf[kk];
        af.x += balv.x; af.y += balv.y; af.z += balv.z; af.w += balv.w;
        *(float4*)(g_AF + o) = af;
    }
}

// ---------------- kernel 4: fused per-query (R13 + FFMA2 matvec) -------------
struct P2 {
    const float *qxyz, *sxyz;
    const int   *qmask;
    const float *Wth1, *bth1, *Wth2, *bth2;
    const float *gt, *bet, *rmt, *rvt, *gg, *beg, *rmg, *rvg;
    float* out;
};

constexpr int OFF_WG   = 0;
constexpr int OFF_WEFF = 4096;
constexpr int OFF_CC   = 4352;
constexpr int OFF_BN   = 4416;
constexpr int OFF_Q    = 4672;
constexpr int QO_DL = 0, QO_POS = 2304, QO_FM = 2432, QO_KIDX = 2464;
constexpr int QSZ = 2496;
constexpr int SMEM_FLOATS = OFF_Q + 4 * QSZ;

__global__ __launch_bounds__(128, 2) void k_main(P2 p) {
    extern __shared__ float sm[];
    int tid = threadIdx.x;

    {
        for (int i = tid; i < 4096; i += 128) {
            int o = i >> 6, in = i & 63;
            sm[OFF_WG + in * 64 + o] = g_Wgeff[i];
        }
        for (int i = tid; i < 256; i += 128) {
            int cc = i >> 2, j = i & 3;
            float acc;
            if (j < 3) {
                acc = 0.f;
                for (int c2 = 0; c2 < 64; ++c2)
                    acc = fmaf(p.Wth2[cc * 64 + c2], p.Wth1[c2 * 3 + j], acc);
            } else {
                acc = p.bth2[cc];
                for (int c2 = 0; c2 < 64; ++c2)
                    acc = fmaf(p.Wth2[cc * 64 + c2], p.bth1[c2], acc);
            }
            sm[OFF_WEFF + cc * 4 + j] = acc;
        }
        if (tid < 64) {
            int i = tid;
            sm[OFF_CC + i] = g_bconst[i];
            float it = p.gt[i] * rsqrtf(p.rvt[i] + EPSV);
            sm[OFF_BN + 0 * 64 + i] = it;
            sm[OFF_BN + 1 * 64 + i] = p.bet[i] - p.rmt[i] * it;
            float ig = p.gg[i] * rsqrtf(p.rvg[i] + EPSV);
            sm[OFF_BN + 2 * 64 + i] = ig;
            sm[OFF_BN + 3 * 64 + i] = p.beg[i] - p.rmg[i] * ig;
        }
    }
    __syncthreads();

    int pr = tid >> 6;
    int t  = tid & 63;
    int g  = t & 7;
    int cq = t >> 3;
    int c0 = cq * 8;
    int k0 = g * 4;

    float* QA = sm + OFF_Q + (pr * 2 + 0) * QSZ;
    float* QB = sm + OFF_Q + (pr * 2 + 1) * QSZ;

    const int ngrp = (BB * NN) / 4;
    for (int grp = blockIdx.x; grp < ngrp; grp += gridDim.x) {
        int b  = (grp * 4) >> 12;
        long rowbase = (long)b * MM;

        {
            int qq = tid >> 5;
            int k  = tid & 31;
            int qi = grp * 4 + qq;
            float* Q = sm + OFF_Q + qq * QSZ;
            int ki = g_idx[qi * KK + k];
            ((int*)(Q + QO_KIDX))[k] = ki;
            float qx = p.qxyz[qi * 3 + 0];
            float qy = p.qxyz[qi * 3 + 1];
            float qz = p.qxyz[qi * 3 + 2];
            const float* s = p.sxyz + (rowbase + ki) * 3;
            float4 pp;
            pp.x = (s[0] - qx) * (1.0f / RADIUS);
            pp.y = (s[1] - qy) * (1.0f / RADIUS);
            pp.z = (s[2] - qz) * (1.0f / RADIUS);
            pp.w = 0.f;
            *(float4*)(Q + QO_POS + k * 4) = pp;
            unsigned nb = g_nbr[qi];
            int qm = p.qmask[qi];
            (Q + QO_FM)[k] = (float)((nb >> k) & 1u) + (1.0f - (float)qm);
        }
        __syncthreads();   // S1

        {
            float4 invtL = *(const float4*)(sm + OFF_BN + 0 * 64 + c0);
            float4 invtH = *(const float4*)(sm + OFF_BN + 0 * 64 + c0 + 4);
            float4 shtL  = *(const float4*)(sm + OFF_BN + 1 * 64 + c0);
            float4 shtH  = *(const float4*)(sm + OFF_BN + 1 * 64 + c0 + 4);
            float4 pA[4], pB[4];
#pragma unroll
            for (int kk = 0; kk < 4; ++kk) {
                pA[kk] = *(const float4*)(QA + QO_POS + (k0 + kk) * 4);
                pB[kk] = *(const float4*)(QB + QO_POS + (k0 + kk) * 4);
            }
#pragma unroll
            for (int j = 0; j < 8; ++j) {
                float4 wej = *(const float4*)(sm + OFF_WEFF + (c0 + j) * 4);
                float it = (j < 4) ? (&invtL.x)[j] : (&invtH.x)[j - 4];
                float sh = (j < 4) ? (&shtL.x)[j] : (&shtH.x)[j - 4];
                float4 rA, rB;
#pragma unroll
                for (int kk = 0; kk < 4; ++kk) {
                    float dA = wej.w, dB = wej.w;
                    dA = fmaf(wej.x, pA[kk].x, dA); dB = fmaf(wej.x, pB[kk].x, dB);
                    dA = fmaf(wej.y, pA[kk].y, dA); dB = fmaf(wej.y, pB[kk].y, dB);
                    dA = fmaf(wej.z, pA[kk].z, dA); dB = fmaf(wej.z, pB[kk].z, dB);
                    (&rA.x)[kk] = fmaxf(fmaf(dA, it, sh), 0.f);
                    (&rB.x)[kk] = fmaxf(fmaf(dB, it, sh), 0.f);
                }
                *(float4*)(QA + QO_DL + (c0 + j) * STRD + k0) = rA;
                *(float4*)(QB + QO_DL + (c0 + j) * STRD + k0) = rB;
            }
        }
        __syncthreads();   // S2

        // ---- matvec via packed FFMA2: pairs of k per 64-bit lane ----
        u64 accA2[16], accB2[16];
#pragma unroll
        for (int i = 0; i < 16; ++i) { accA2[i] = 0ull; accB2[i] = 0ull; }
        {
            const float* W  = sm + OFF_WG + c0;
            const float* dA = QA + QO_DL + k0;
            const float* dB = QB + QO_DL + k0;
#pragma unroll 2
            for (int c2 = 0; c2 < 64; ++c2) {
                float4 w0 = *(const float4*)(W + c2 * 64);
                float4 w1 = *(const float4*)(W + c2 * 64 + 4);
                ulonglong2 a2 = *(const ulonglong2*)(dA + c2 * STRD);
                ulonglong2 b2 = *(const ulonglong2*)(dB + c2 * STRD);
#pragma unroll
                for (int j = 0; j < 8; ++j) {
                    float wv = (j < 4) ? (&w0.x)[j] : (&w1.x)[j - 4];
                    u64 w2 = pk2(wv);
                    FMA2(accA2[j * 2 + 0], w2, a2.x);
                    FMA2(accA2[j * 2 + 1], w2, a2.y);
                    FMA2(accB2[j * 2 + 0], w2, b2.x);
                    FMA2(accB2[j * 2 + 1], w2, b2.y);
                }
            }
        }
        float accA[32], accB[32];
#pragma unroll
        for (int j = 0; j < 8; ++j) {
            UNPK(accA[j * 4 + 0], accA[j * 4 + 1], accA2[j * 2 + 0]);
            UNPK(accA[j * 4 + 2], accA[j * 4 + 3], accA2[j * 2 + 1]);
            UNPK(accB[j * 4 + 0], accB[j * 4 + 1], accB2[j * 2 + 0]);
            UNPK(accB[j * 4 + 2], accB[j * 4 + 3], accB2[j * 2 + 1]);
        }

        float4 bcnL  = *(const float4*)(sm + OFF_CC + c0);
        float4 bcnH  = *(const float4*)(sm + OFF_CC + c0 + 4);
        float4 invgL = *(const float4*)(sm + OFF_BN + 2 * 64 + c0);
        float4 invgH = *(const float4*)(sm + OFF_BN + 2 * 64 + c0 + 4);
        float4 shgL  = *(const float4*)(sm + OFF_BN + 3 * 64 + c0);
        float4 shgH  = *(const float4*)(sm + OFF_BN + 3 * 64 + c0 + 4);
#pragma unroll
        for (int qq = 0; qq < 2; ++qq) {
            int qi = grp * 4 + pr * 2 + qq;
            int n  = qi & (NN - 1);
            float* Q = qq ? QB : QA;
            float* acc = qq ? accB : accA;
            int* kidx = (int*)(Q + QO_KIDX);
            float* fmB = Q + QO_FM;

            float4 dl4[8];
#pragma unroll
            for (int j = 0; j < 8; ++j)
                dl4[j] = *(const float4*)(Q + QO_DL + (c0 + j) * STRD + k0);

            int nn = g_idxnn[qi];
            float4 qiL = *(const float4*)(g_Qi + (rowbase + nn) * 64 + c0);
            float4 qiH = *(const float4*)(g_Qi + (rowbase + nn) * 64 + c0 + 4);
            float se[8] = {0.f, 0.f, 0.f, 0.f, 0.f, 0.f, 0.f, 0.f};
            float sf[8] = {0.f, 0.f, 0.f, 0.f, 0.f, 0.f, 0.f, 0.f};
#pragma unroll
            for (int kk = 0; kk < 4; ++kk) {
                int k = k0 + kk;
                int ridx = kidx[k];
                float4 qjL = *(const float4*)(g_Qj + (rowbase + ridx) * 64 + c0);
                float4 qjH = *(const float4*)(g_Qj + (rowbase + ridx) * 64 + c0 + 4);
                float4 afL = *(const float4*)(g_AF + (rowbase + ridx) * 64 + c0);
                float4 afH = *(const float4*)(g_AF + (rowbase + ridx) * 64 + c0 + 4);
                float fm = fmB[k];
#pragma unroll
                for (int j = 0; j < 8; ++j) {
                    float qiv = (j < 4) ? (&qiL.x)[j] : (&qiH.x)[j - 4];
                    float qjv = (j < 4) ? (&qjL.x)[j] : (&qjH.x)[j - 4];
                    float afv = (j < 4) ? (&afL.x)[j] : (&afH.x)[j - 4];
                    float bc  = (j < 4) ? (&bcnL.x)[j] : (&bcnH.x)[j - 4];
                    float ig  = (j < 4) ? (&invgL.x)[j] : (&invgH.x)[j - 4];
                    float sg  = (j < 4) ? (&shgL.x)[j] : (&shgH.x)[j - 4];
                    float pre2 = qiv - qjv + acc[j * 4 + kk] + bc;
                    float v = fmaxf(fmaf(pre2, ig, sg), 0.f);
                    float e = __expf(v);
                    float ftv = (afv + (&dl4[j].x)[kk]) * fm;
                    se[j] += e;
                    sf[j] = fmaf(e, ftv, sf[j]);
                }
            }
#pragma unroll
            for (int j = 0; j < 8; ++j) {
                float s1 = se[j], s2 = sf[j];
                s1 += __shfl_xor_sync(0xffffffffu, s1, 1);
                s2 += __shfl_xor_sync(0xffffffffu, s2, 1);
                s1 += __shfl_xor_sync(0xffffffffu, s1, 2);
                s2 += __shfl_xor_sync(0xffffffffu, s2, 2);
                s1 += __shfl_xor_sync(0xffffffffu, s1, 4);
                s2 += __shfl_xor_sync(0xffffffffu, s2, 4);
                if (g == 0)
                    p.out[((long)b * CCH + c0 + j) * NN + n] = s2 / s1;
            }
        }
        __syncthreads();   // S3
    }
}

// ---------------- host launcher ----------------
extern "C" void kernel_launch(void* const* d_in, const int* in_sizes, int n_in,
                              void* d_out, int out_size) {
    const float* qxyz  = (const float*)d_in[0];
    const float* sxyz  = (const float*)d_in[1];
    const int*   qmask = (const int*)d_in[2];
    const int*   smask = (const int*)d_in[3];
    const float* feat  = (const float*)d_in[4];
    const float* Wth1  = (const float*)d_in[5];
    const float* bth1  = (const float*)d_in[6];
    const float* Wth2  = (const float*)d_in[7];
    const float* bth2  = (const float*)d_in[8];
    const float* Wphi  = (const float*)d_in[9];
    const float* bphi  = (const float*)d_in[10];
    const float* Wpsi  = (const float*)d_in[11];
    const float* bpsi  = (const float*)d_in[12];
    const float* Wal   = (const float*)d_in[13];
    const float* bal   = (const float*)d_in[14];
    const float* Wg1   = (const float*)d_in[15];
    const float* bg1   = (const float*)d_in[16];
    const float* Wg2   = (const float*)d_in[17];
    const float* bg2   = (const float*)d_in[18];

    P2 p;
    p.qxyz = qxyz; p.sxyz = sxyz; p.qmask = qmask;
    p.Wth1 = Wth1; p.bth1 = bth1; p.Wth2 = Wth2; p.bth2 = bth2;
    p.gt   = (const float*)d_in[19]; p.bet  = (const float*)d_in[20];
    p.rmt  = (const float*)d_in[21]; p.rvt  = (const float*)d_in[22];
    p.gg   = (const float*)d_in[23]; p.beg  = (const float*)d_in[24];
    p.rmg  = (const float*)d_in[25]; p.rvg  = (const float*)d_in[26];
    p.out  = (float*)d_out;

    k_compose1<<<16, 256>>>(Wg1, Wg2, Wal);
    k_compose2<<<16, 256>>>(Wphi, Wpsi, bphi, bpsi, bg1, bg2, Wg2);

    cudaFuncSetAttribute(k_knn, cudaFuncAttributeMaxDynamicSharedMemorySize,
                         KNN_SM_FLOATS * 4);
    k_knn<<<(BB * NN) / 16, 256, KNN_SM_FLOATS * 4>>>(qxyz, sxyz, smask);

    cudaFuncSetAttribute(k_pre, cudaFuncAttributeMaxDynamicSharedMemorySize,
                         PRE_SM * 4);
    k_pre<<<(BB * MM) / 64, 128, PRE_SM * 4>>>(feat, bal);

    cudaFuncSetAttribute(k_main, cudaFuncAttributeMaxDynamicSharedMemorySize,
                         SMEM_FLOATS * 4);
    int dev = 0, nsm = 148;
    cudaGetDevice(&dev);
    cudaDeviceGetAttribute(&nsm, cudaDevAttrMultiProcessorCount, dev);
    k_main<<<2 * nsm, 128, SMEM_FLOATS * 4>>>(p);
}